// round 1
// baseline (speedup 1.0000x reference)
#include <cuda_runtime.h>
#include <math.h>

#define S_SAMPLES 512
#define VDIM      128
#define NVOX      (VDIM * VDIM * VDIM)   // 2097152
#define DET       128
#define NPIX      (DET * DET)            // 16384

// 4 binary occupancy volumes: slice = batch*2 + view  (view 0 = frontal, 1 = lateral)
__device__ __align__(16) unsigned char g_vol[4][NVOX];   // 8 MB
__device__ double g_acc;

// ---------------------------------------------------------------------------
// Zero volumes + accumulator (one pass, uint4 stores; 4*NVOX = 8 MB / 16 = 524288)
// ---------------------------------------------------------------------------
__global__ void zero_kernel() {
    unsigned int i = blockIdx.x * blockDim.x + threadIdx.x;
    uint4 z; z.x = z.y = z.z = z.w = 0u;
    if (i < (4u * NVOX) / 16u) {
        reinterpret_cast<uint4*>(g_vol)[i] = z;
    }
    if (i == 0) g_acc = 0.0;
}

// ---------------------------------------------------------------------------
// Backprojection: one thread per ray; clip sample range to the voxel box,
// then march and write 1s (racy-but-idempotent byte stores).
// ---------------------------------------------------------------------------
__global__ void bp_kernel(const float* __restrict__ predF,
                          const float* __restrict__ predL,
                          const float* __restrict__ srcF,
                          const float* __restrict__ tgtF,
                          const float* __restrict__ srcL,
                          const float* __restrict__ tgtL,
                          const float* __restrict__ Ainv,
                          const float* __restrict__ tinv)
{
    int p = blockIdx.x * blockDim.x + threadIdx.x;
    if (p >= NPIX) return;
    int slice = blockIdx.y;          // 0..3
    int view  = slice & 1;           // 0 = frontal, 1 = lateral
    int batch = slice >> 1;

    const float* mask = (view ? predL : predF) + batch * NPIX;
    if (!(mask[p] > 0.5f)) return;   // inactive pixel: no scatter at all

    const float* src = view ? srcL : srcF;
    const float* tgt = (view ? tgtL : tgtF) + 3 * p;

    float sx = src[0], sy = src[1], sz = src[2];
    float dx = tgt[0] - sx, dy = tgt[1] - sy, dz = tgt[2] - sz;
    float len = sqrtf(dx * dx + dy * dy + dz * dz);
    float inv = 1.0f / (len + 1e-8f);
    dx *= inv; dy *= inv; dz *= inv;
    float L = len * 2.5f;

    float a00 = Ainv[0], a01 = Ainv[1], a02 = Ainv[2];
    float a10 = Ainv[3], a11 = Ainv[4], a12 = Ainv[5];
    float a20 = Ainv[6], a21 = Ainv[7], a22 = Ainv[8];
    float t0 = tinv[0], t1 = tinv[1], t2 = tinv[2];

    // Voxel-space ray (affine in t) — used ONLY to bound the sample range.
    float q0x = a00 * sx + a01 * sy + a02 * sz + t0;
    float q0y = a10 * sx + a11 * sy + a12 * sz + t1;
    float q0z = a20 * sx + a21 * sy + a22 * sz + t2;
    float qdx = a00 * dx + a01 * dy + a02 * dz;
    float qdy = a10 * dx + a11 * dy + a12 * dz;
    float qdz = a20 * dx + a21 * dy + a22 * dz;

    const float LOQ = -0.501f;                  // round() valid window with margin
    const float HIQ = (float)VDIM - 0.499f;
    float tlo = 0.0f, thi = L;
    {
        float q0a[3] = {q0x, q0y, q0z};
        float qda[3] = {qdx, qdy, qdz};
        #pragma unroll
        for (int ax = 0; ax < 3; ax++) {
            float q0 = q0a[ax], qd = qda[ax];
            if (fabsf(qd) < 1e-9f) {
                if (q0 < LOQ || q0 > HIQ) { tlo = 1.0f; thi = 0.0f; }
            } else {
                float u1 = (LOQ - q0) / qd;
                float u2 = (HIQ - q0) / qd;
                tlo = fmaxf(tlo, fminf(u1, u2));
                thi = fminf(thi, fmaxf(u1, u2));
            }
        }
    }
    if (thi < tlo) return;

    float dt = L * (1.0f / (S_SAMPLES - 1));
    int klo = max(0,             (int)floorf(tlo / dt) - 2);   // safety margin:
    int khi = min(S_SAMPLES - 1, (int)ceilf (thi / dt) + 2);   // per-sample check is authoritative

    unsigned char* vol = g_vol[slice];
    for (int k = klo; k <= khi; k++) {
        float tv = (float)k * (1.0f / (S_SAMPLES - 1));   // matches jnp.linspace(0,1,S)
        float t  = tv * L;
        float wx = fmaf(dx, t, sx);
        float wy = fmaf(dy, t, sy);
        float wz = fmaf(dz, t, sz);
        float qx = a00 * wx + a01 * wy + a02 * wz + t0;
        float qy = a10 * wx + a11 * wy + a12 * wz + t1;
        float qz = a20 * wx + a21 * wy + a22 * wz + t2;
        int vx = (int)rintf(qx);   // rintf = ties-to-even, identical to jnp.round
        int vy = (int)rintf(qy);
        int vz = (int)rintf(qz);
        if ((unsigned)vx < (unsigned)VDIM &&
            (unsigned)vy < (unsigned)VDIM &&
            (unsigned)vz < (unsigned)VDIM) {
            vol[(vx * VDIM + vy) * VDIM + vz] = 1;   // idempotent racy store
        }
    }
}

// ---------------------------------------------------------------------------
// BCE reduction.  s = volF+volL in {0,1,2}; log sigmoid(s) = b[s] + s, so
// term = g*log(p) + (1-g)*log(1-p) = b[s] + g*s  with b[s] = log(1-sigmoid(s)).
// ---------------------------------------------------------------------------
__device__ __forceinline__ float bce_term(float g, int s) {
    float b = (s == 0) ? -0.69314718055994531f
            : (s == 1) ? -1.31326168751822287f
                       : -2.12692801104297263f;
    return fmaf(g, (float)s, b);
}

__device__ __forceinline__ float warp_sum(float v) {
    #pragma unroll
    for (int o = 16; o > 0; o >>= 1) v += __shfl_down_sync(0xffffffffu, v, o);
    return v;
}

__global__ void reduce_kernel(const float* __restrict__ gt)
{
    unsigned int i = blockIdx.x * blockDim.x + threadIdx.x;   // float4 / uchar4 index
    float sum = 0.0f;
    if (i < NVOX / 4u) {
        float4 g  = reinterpret_cast<const float4*>(gt)[i];
        uchar4 f0 = reinterpret_cast<const uchar4*>(g_vol[0])[i];
        uchar4 l0 = reinterpret_cast<const uchar4*>(g_vol[1])[i];
        uchar4 f1 = reinterpret_cast<const uchar4*>(g_vol[2])[i];
        uchar4 l1 = reinterpret_cast<const uchar4*>(g_vol[3])[i];
        sum += bce_term(g.x, f0.x + l0.x) + bce_term(g.x, f1.x + l1.x);
        sum += bce_term(g.y, f0.y + l0.y) + bce_term(g.y, f1.y + l1.y);
        sum += bce_term(g.z, f0.z + l0.z) + bce_term(g.z, f1.z + l1.z);
        sum += bce_term(g.w, f0.w + l0.w) + bce_term(g.w, f1.w + l1.w);
    }
    sum = warp_sum(sum);
    __shared__ float sh[32];
    int lane = threadIdx.x & 31, w = threadIdx.x >> 5;
    if (lane == 0) sh[w] = sum;
    __syncthreads();
    if (w == 0) {
        float v = (lane < (int)(blockDim.x >> 5)) ? sh[lane] : 0.0f;
        v = warp_sum(v);
        if (lane == 0) atomicAdd(&g_acc, (double)v);
    }
}

__global__ void finalize_kernel(float* __restrict__ out)
{
    // total = (1/B) * sum_i [ -(1/N) * S_i ] = -(S0+S1) / (2*N)
    out[0] = (float)(-g_acc / (2.0 * (double)NVOX));
}

// ---------------------------------------------------------------------------
extern "C" void kernel_launch(void* const* d_in, const int* in_sizes, int n_in,
                              void* d_out, int out_size)
{
    const float* predF = (const float*)d_in[0];
    const float* predL = (const float*)d_in[1];
    const float* srcF  = (const float*)d_in[2];
    const float* tgtF  = (const float*)d_in[3];
    const float* srcL  = (const float*)d_in[4];
    const float* tgtL  = (const float*)d_in[5];
    const float* gt    = (const float*)d_in[6];
    const float* Ainv  = (const float*)d_in[7];
    const float* tinv  = (const float*)d_in[8];
    float* out = (float*)d_out;

    // zero: 8 MB / 16B per thread = 524288 threads
    zero_kernel<<<(4 * NVOX / 16 + 255) / 256, 256>>>();

    dim3 bp_grid((NPIX + 255) / 256, 4);
    bp_kernel<<<bp_grid, 256>>>(predF, predL, srcF, tgtF, srcL, tgtL, Ainv, tinv);

    reduce_kernel<<<(NVOX / 4 + 255) / 256, 256>>>(gt);
    finalize_kernel<<<1, 1>>>(out);
}

// round 2
// speedup vs baseline: 1.5000x; 1.5000x over previous
#include <cuda_runtime.h>
#include <math.h>

#define S_SAMPLES 512
#define VDIM      128
#define NVOX      (VDIM * VDIM * VDIM)   // 2097152
#define DET       128
#define NPIX      (DET * DET)            // 16384

// 4 binary occupancy volumes, slice = batch*2 + view (view 0 = frontal, 1 = lateral).
// Frontal volumes use TRANSPOSED layout (vx, vz, vy) so warp-lane stores (lanes
// differ in vy) are contiguous. Lateral volumes use natural (vx, vy, vz) layout
// (lanes differ in vz -> already contiguous).
// Invariant: g_vol is all-zero at entry to kernel_launch (static init + the
// reduce kernel consumes-and-rezeroes it every call).
__device__ __align__(16) unsigned char g_vol[4][NVOX];   // 8 MB
__device__ double       g_acc = 0.0;
__device__ unsigned int g_ctr = 0;

// ---------------------------------------------------------------------------
// Backprojection: one thread per ray; clip sample range to the voxel box,
// then march and write 1s (racy-but-idempotent byte stores).
// ---------------------------------------------------------------------------
__global__ void bp_kernel(const float* __restrict__ predF,
                          const float* __restrict__ predL,
                          const float* __restrict__ srcF,
                          const float* __restrict__ tgtF,
                          const float* __restrict__ srcL,
                          const float* __restrict__ tgtL,
                          const float* __restrict__ Ainv,
                          const float* __restrict__ tinv)
{
    int p = blockIdx.x * blockDim.x + threadIdx.x;
    if (p >= NPIX) return;
    int slice = blockIdx.y;          // 0..3
    int view  = slice & 1;           // 0 = frontal, 1 = lateral
    int batch = slice >> 1;

    const float* mask = (view ? predL : predF) + batch * NPIX;
    if (!(mask[p] > 0.5f)) return;   // inactive pixel: no scatter at all

    const float* src = view ? srcL : srcF;
    const float* tgt = (view ? tgtL : tgtF) + 3 * p;

    float sx = src[0], sy = src[1], sz = src[2];
    float dx = tgt[0] - sx, dy = tgt[1] - sy, dz = tgt[2] - sz;
    float len = sqrtf(dx * dx + dy * dy + dz * dz);
    float inv = 1.0f / (len + 1e-8f);
    dx *= inv; dy *= inv; dz *= inv;
    float L = len * 2.5f;

    float a00 = Ainv[0], a01 = Ainv[1], a02 = Ainv[2];
    float a10 = Ainv[3], a11 = Ainv[4], a12 = Ainv[5];
    float a20 = Ainv[6], a21 = Ainv[7], a22 = Ainv[8];
    float t0 = tinv[0], t1 = tinv[1], t2 = tinv[2];

    // Voxel-space ray (affine in t) — used ONLY to bound the sample range.
    float q0x = a00 * sx + a01 * sy + a02 * sz + t0;
    float q0y = a10 * sx + a11 * sy + a12 * sz + t1;
    float q0z = a20 * sx + a21 * sy + a22 * sz + t2;
    float qdx = a00 * dx + a01 * dy + a02 * dz;
    float qdy = a10 * dx + a11 * dy + a12 * dz;
    float qdz = a20 * dx + a21 * dy + a22 * dz;

    const float LOQ = -0.501f;                  // round() valid window with margin
    const float HIQ = (float)VDIM - 0.499f;
    float tlo = 0.0f, thi = L;
    {
        float q0a[3] = {q0x, q0y, q0z};
        float qda[3] = {qdx, qdy, qdz};
        #pragma unroll
        for (int ax = 0; ax < 3; ax++) {
            float q0 = q0a[ax], qd = qda[ax];
            if (fabsf(qd) < 1e-9f) {
                if (q0 < LOQ || q0 > HIQ) { tlo = 1.0f; thi = 0.0f; }
            } else {
                float u1 = (LOQ - q0) / qd;
                float u2 = (HIQ - q0) / qd;
                tlo = fmaxf(tlo, fminf(u1, u2));
                thi = fminf(thi, fmaxf(u1, u2));
            }
        }
    }
    if (thi < tlo) return;

    float dt = L * (1.0f / (S_SAMPLES - 1));
    int klo = max(0,             (int)floorf(tlo / dt) - 2);   // safety margin:
    int khi = min(S_SAMPLES - 1, (int)ceilf (thi / dt) + 2);   // per-sample check is authoritative

    unsigned char* vol = g_vol[slice];
    for (int k = klo; k <= khi; k++) {
        float tv = (float)k * (1.0f / (S_SAMPLES - 1));   // matches jnp.linspace(0,1,S)
        float t  = tv * L;
        float wx = fmaf(dx, t, sx);
        float wy = fmaf(dy, t, sy);
        float wz = fmaf(dz, t, sz);
        float qx = a00 * wx + a01 * wy + a02 * wz + t0;
        float qy = a10 * wx + a11 * wy + a12 * wz + t1;
        float qz = a20 * wx + a21 * wy + a22 * wz + t2;
        int vx = (int)rintf(qx);   // rintf = ties-to-even, identical to jnp.round
        int vy = (int)rintf(qy);
        int vz = (int)rintf(qz);
        if ((unsigned)vx < (unsigned)VDIM &&
            (unsigned)vy < (unsigned)VDIM &&
            (unsigned)vz < (unsigned)VDIM) {
            // view 0 (frontal): transposed (vx, vz, vy) -> lanes contiguous in vy
            // view 1 (lateral): natural    (vx, vy, vz) -> lanes contiguous in vz
            int idx = view ? ((vx * VDIM + vy) * VDIM + vz)
                           : ((vx * VDIM + vz) * VDIM + vy);
            vol[idx] = 1;   // idempotent racy store
        }
    }
}

// ---------------------------------------------------------------------------
// BCE + finalize + volume re-zero, fused.
//   s = volF+volL in {0,1,2};  term = g*log(p) + (1-g)*log(1-p) = b[s] + g*s
//   with b[s] = log(1 - sigmoid(s)).
// One block per vx-plane. Frontal volumes are read via a shared-memory
// transpose (they are stored (vx, vz, vy)); lateral + gt read directly.
// Every byte of g_vol read here is immediately re-zeroed for the next call.
// Last block divides and writes the output (self-resetting counter).
// ---------------------------------------------------------------------------
__device__ __forceinline__ float bce_term(float g, int s) {
    float b = (s == 0) ? -0.69314718055994531f
            : (s == 1) ? -1.31326168751822287f
                       : -2.12692801104297263f;
    return fmaf(g, (float)s, b);
}

__device__ __forceinline__ float warp_sum(float v) {
    #pragma unroll
    for (int o = 16; o > 0; o >>= 1) v += __shfl_down_sync(0xffffffffu, v, o);
    return v;
}

#define SROW 132   // smem row stride in bytes (128 + 4 pad)

__global__ void reduce_kernel(const float* __restrict__ gt, float* __restrict__ out)
{
    __shared__ unsigned char sF0[VDIM * SROW];   // frontal batch 0, plane transposed
    __shared__ unsigned char sF1[VDIM * SROW];   // frontal batch 1
    __shared__ float sh[32];

    int vx = blockIdx.x;          // one 128x128 plane per block
    int t  = threadIdx.x;         // 256 threads

    // --- load + transpose + zero the two frontal planes -------------------
    // Plane bytes are at global offset vx*16384 + vz*128 + vy (transposed store
    // layout). A 16B-aligned chunk stays within one vz row.
    uint4 z4; z4.x = z4.y = z4.z = z4.w = 0u;
    #pragma unroll
    for (int it = 0; it < 4; it++) {
        int o16   = it * 256 + t;           // uint4 index within plane (0..1023)
        int byteo = o16 * 16;
        int vz = byteo >> 7;
        int vy = byteo & 127;
        uint4* pF0 = reinterpret_cast<uint4*>(g_vol[0] + (size_t)vx * 16384) + o16;
        uint4* pF1 = reinterpret_cast<uint4*>(g_vol[2] + (size_t)vx * 16384) + o16;
        uint4 a = *pF0; *pF0 = z4;          // consume-and-reset
        uint4 b = *pF1; *pF1 = z4;
        unsigned int* d0 = reinterpret_cast<unsigned int*>(&sF0[vz * SROW + vy]); // 4B aligned
        unsigned int* d1 = reinterpret_cast<unsigned int*>(&sF1[vz * SROW + vy]);
        d0[0] = a.x; d0[1] = a.y; d0[2] = a.z; d0[3] = a.w;
        d1[0] = b.x; d1[1] = b.y; d1[2] = b.z; d1[3] = b.w;
    }
    __syncthreads();

    // --- compute ----------------------------------------------------------
    float sum = 0.0f;
    int c   = t & 31;         // uchar4 column along vz
    int vyw = t >> 5;         // warp's starting vy
    uchar4 zc; zc.x = zc.y = zc.z = zc.w = 0;
    for (int vy = vyw; vy < VDIM; vy += 8) {
        int idx4 = vx * 4096 + vy * 32 + c;               // uchar4 / float4 index
        uchar4 L0 = reinterpret_cast<const uchar4*>(g_vol[1])[idx4];
        uchar4 L1 = reinterpret_cast<const uchar4*>(g_vol[3])[idx4];
        reinterpret_cast<uchar4*>(g_vol[1])[idx4] = zc;   // consume-and-reset
        reinterpret_cast<uchar4*>(g_vol[3])[idx4] = zc;
        float4 g = reinterpret_cast<const float4*>(gt)[idx4];
        int vz0 = 4 * c;
        unsigned char f0x = sF0[(vz0 + 0) * SROW + vy];
        unsigned char f0y = sF0[(vz0 + 1) * SROW + vy];
        unsigned char f0z = sF0[(vz0 + 2) * SROW + vy];
        unsigned char f0w = sF0[(vz0 + 3) * SROW + vy];
        unsigned char f1x = sF1[(vz0 + 0) * SROW + vy];
        unsigned char f1y = sF1[(vz0 + 1) * SROW + vy];
        unsigned char f1z = sF1[(vz0 + 2) * SROW + vy];
        unsigned char f1w = sF1[(vz0 + 3) * SROW + vy];
        sum += bce_term(g.x, f0x + L0.x) + bce_term(g.x, f1x + L1.x);
        sum += bce_term(g.y, f0y + L0.y) + bce_term(g.y, f1y + L1.y);
        sum += bce_term(g.z, f0z + L0.z) + bce_term(g.z, f1z + L1.z);
        sum += bce_term(g.w, f0w + L0.w) + bce_term(g.w, f1w + L1.w);
    }

    // --- block reduce -> global atomic -> last-block finalize -------------
    sum = warp_sum(sum);
    int lane = t & 31, w = t >> 5;
    if (lane == 0) sh[w] = sum;
    __syncthreads();
    if (w == 0) {
        float v = (lane < 8) ? sh[lane] : 0.0f;
        v = warp_sum(v);
        if (lane == 0) {
            atomicAdd(&g_acc, (double)v);
            __threadfence();
            unsigned int done = atomicInc(&g_ctr, gridDim.x - 1);  // self-resetting
            if (done == gridDim.x - 1) {
                double acc = atomicAdd(&g_acc, 0.0);               // atomic read
                out[0] = (float)(-acc / (2.0 * (double)NVOX));     // /B /NVOX
                g_acc = 0.0;                                       // reset for next call
            }
        }
    }
}

// ---------------------------------------------------------------------------
extern "C" void kernel_launch(void* const* d_in, const int* in_sizes, int n_in,
                              void* d_out, int out_size)
{
    const float* predF = (const float*)d_in[0];
    const float* predL = (const float*)d_in[1];
    const float* srcF  = (const float*)d_in[2];
    const float* tgtF  = (const float*)d_in[3];
    const float* srcL  = (const float*)d_in[4];
    const float* tgtL  = (const float*)d_in[5];
    const float* gt    = (const float*)d_in[6];
    const float* Ainv  = (const float*)d_in[7];
    const float* tinv  = (const float*)d_in[8];
    float* out = (float*)d_out;

    dim3 bp_grid((NPIX + 255) / 256, 4);
    bp_kernel<<<bp_grid, 256>>>(predF, predL, srcF, tgtF, srcL, tgtL, Ainv, tinv);

    reduce_kernel<<<VDIM, 256>>>(gt, out);
}

// round 3
// speedup vs baseline: 1.9898x; 1.3266x over previous
#include <cuda_runtime.h>
#include <math.h>

#define S_SAMPLES 512
#define VDIM      128
#define NVOX      (VDIM * VDIM * VDIM)   // 2097152
#define DET       128
#define NPIX      (DET * DET)            // 16384

// 4 binary occupancy volumes, slice = batch*2 + view (view 0 = frontal, 1 = lateral).
// Frontal volumes use TRANSPOSED layout (vx, vz, vy) so warp-lane scatter stores
// (lanes differ in vy) are contiguous. Lateral volumes use natural (vx, vy, vz)
// (lanes differ in vz -> already contiguous).
// Invariant: g_vol is all-zero at entry to kernel_launch (static init + the
// reduce kernel consumes-and-rezeroes every byte it reads).
__device__ __align__(16) unsigned char g_vol[4][NVOX];   // 8 MB
__device__ double       g_acc = 0.0;
__device__ unsigned int g_ctr = 0;

// ---------------------------------------------------------------------------
// Backprojection: one thread per ray; clip sample range to the voxel box,
// then march IN VOXEL SPACE (q(t) is affine in t) writing idempotent 1s.
// ---------------------------------------------------------------------------
__global__ void bp_kernel(const float* __restrict__ predF,
                          const float* __restrict__ predL,
                          const float* __restrict__ srcF,
                          const float* __restrict__ tgtF,
                          const float* __restrict__ srcL,
                          const float* __restrict__ tgtL,
                          const float* __restrict__ Ainv,
                          const float* __restrict__ tinv)
{
    int p = blockIdx.x * blockDim.x + threadIdx.x;
    if (p >= NPIX) return;
    int slice = blockIdx.y;          // 0..3
    int view  = slice & 1;           // 0 = frontal, 1 = lateral
    int batch = slice >> 1;

    const float* mask = (view ? predL : predF) + batch * NPIX;
    if (!(mask[p] > 0.5f)) return;   // inactive pixel: nothing to do

    const float* src = view ? srcL : srcF;
    const float* tgt = (view ? tgtL : tgtF) + 3 * p;

    float sx = src[0], sy = src[1], sz = src[2];
    float dx = tgt[0] - sx, dy = tgt[1] - sy, dz = tgt[2] - sz;
    float len = sqrtf(dx * dx + dy * dy + dz * dz);
    float inv = 1.0f / (len + 1e-8f);
    dx *= inv; dy *= inv; dz *= inv;
    float L = len * 2.5f;

    float a00 = Ainv[0], a01 = Ainv[1], a02 = Ainv[2];
    float a10 = Ainv[3], a11 = Ainv[4], a12 = Ainv[5];
    float a20 = Ainv[6], a21 = Ainv[7], a22 = Ainv[8];

    // Voxel-space ray: q(t) = q0 + t*qd   (affine in t)
    float q0x = a00 * sx + a01 * sy + a02 * sz + tinv[0];
    float q0y = a10 * sx + a11 * sy + a12 * sz + tinv[1];
    float q0z = a20 * sx + a21 * sy + a22 * sz + tinv[2];
    float qdx = a00 * dx + a01 * dy + a02 * dz;
    float qdy = a10 * dx + a11 * dy + a12 * dz;
    float qdz = a20 * dx + a21 * dy + a22 * dz;

    const float LOQ = -0.501f;                  // round() valid window with margin
    const float HIQ = (float)VDIM - 0.499f;
    float tlo = 0.0f, thi = L;
    {
        float q0a[3] = {q0x, q0y, q0z};
        float qda[3] = {qdx, qdy, qdz};
        #pragma unroll
        for (int ax = 0; ax < 3; ax++) {
            float q0 = q0a[ax], qd = qda[ax];
            if (fabsf(qd) < 1e-9f) {
                if (q0 < LOQ || q0 > HIQ) { tlo = 1.0f; thi = 0.0f; }
            } else {
                float u1 = (LOQ - q0) / qd;
                float u2 = (HIQ - q0) / qd;
                tlo = fmaxf(tlo, fminf(u1, u2));
                thi = fminf(thi, fmaxf(u1, u2));
            }
        }
    }
    if (thi < tlo) return;

    float dt = L * (1.0f / (S_SAMPLES - 1));
    int klo = max(0,             (int)floorf(tlo / dt) - 2);   // safety margin:
    int khi = min(S_SAMPLES - 1, (int)ceilf (thi / dt) + 2);   // per-sample check authoritative

    // Pre-scale direction by L: q = fma(tv, rd, q0), tv = k/(S-1)
    float rdx = L * qdx, rdy = L * qdy, rdz = L * qdz;
    const float c1 = 1.0f / (S_SAMPLES - 1);

    unsigned char* vol = g_vol[slice];
    for (int k = klo; k <= khi; k++) {
        float tv = (float)k * c1;                      // matches jnp.linspace(0,1,S)
        int vx = __float2int_rn(fmaf(tv, rdx, q0x));   // F2I.rn = ties-to-even (jnp.round)
        int vy = __float2int_rn(fmaf(tv, rdy, q0y));
        int vz = __float2int_rn(fmaf(tv, rdz, q0z));
        if ((unsigned)vx < (unsigned)VDIM &&
            (unsigned)vy < (unsigned)VDIM &&
            (unsigned)vz < (unsigned)VDIM) {
            // view 0 (frontal): transposed (vx, vz, vy) -> lanes contiguous in vy
            // view 1 (lateral): natural    (vx, vy, vz) -> lanes contiguous in vz
            int idx = view ? ((vx * VDIM + vy) * VDIM + vz)
                           : ((vx * VDIM + vz) * VDIM + vy);
            vol[idx] = 1;   // idempotent racy store
        }
    }
}

// ---------------------------------------------------------------------------
// BCE + finalize + volume re-zero, fused.
//   s = volF+volL in {0,1,2};  term = b[s] + g*s,  b[s] = log(1 - sigmoid(s)).
// Grid = 128 planes x 4 vy-quarters (512 blocks, 256 threads) for occupancy.
// Frontal volumes (stored (vx, vz, vy)) are transposed through smem:
//   phase 1 writes sT[vy_local][vz] (byte column-writes; same-word merges),
//   phase 2 reads one aligned conflict-free LDS.32 per 4-vz group.
// Every byte of g_vol read here is immediately re-zeroed for the next call.
// ---------------------------------------------------------------------------
__device__ __forceinline__ float bce_term(float g, int s) {
    float b = (s == 0) ? -0.69314718055994531f
            : (s == 1) ? -1.31326168751822287f
                       : -2.12692801104297263f;
    return fmaf(g, (float)s, b);
}

__device__ __forceinline__ float warp_sum(float v) {
    #pragma unroll
    for (int o = 16; o > 0; o >>= 1) v += __shfl_down_sync(0xffffffffu, v, o);
    return v;
}

#define TROW 132   // smem row stride (vz 128 + 4 pad): word idx = 33*vy + vz/4

__global__ void reduce_kernel(const float* __restrict__ gt, float* __restrict__ out)
{
    __shared__ unsigned char sT0[32 * TROW];   // frontal batch 0: [vy_local][vz]
    __shared__ unsigned char sT1[32 * TROW];   // frontal batch 1
    __shared__ float sh[32];

    int vx  = blockIdx.x;            // plane
    int vy0 = blockIdx.y * 32;       // vy quarter
    int t   = threadIdx.x;           // 256 threads

    // --- phase 1: load + transpose + zero frontal sub-planes ---------------
    // Global frontal layout byte offset: vx*16384 + vz*128 + vy.
    // Thread t: vz row r = t>>1, vy chunk sub = t&1 -> 16 bytes at vy0+16*sub.
    // Warp LDG.128: 16 rows x 32B chunk = 16 sectors (optimal for 512B).
    {
        int r   = t >> 1;
        int sub = t & 1;
        size_t go = (size_t)vx * 16384 + (size_t)r * 128 + vy0 + sub * 16;
        uint4 z4; z4.x = z4.y = z4.z = z4.w = 0u;
        uint4* p0 = reinterpret_cast<uint4*>(g_vol[0] + go);
        uint4* p1 = reinterpret_cast<uint4*>(g_vol[2] + go);
        uint4 a = *p0; *p0 = z4;                 // consume-and-reset
        uint4 b = *p1; *p1 = z4;
        unsigned char ab[16], bb[16];
        *reinterpret_cast<uint4*>(ab) = a;
        *reinterpret_cast<uint4*>(bb) = b;
        int vybase = sub * 16;
        #pragma unroll
        for (int i = 0; i < 16; i++) {           // byte column-writes: lanes hit
            sT0[(vybase + i) * TROW + r] = ab[i];// different bytes of same word
            sT1[(vybase + i) * TROW + r] = bb[i];// -> merged, conflict-free
        }
    }
    __syncthreads();

    // --- phase 2: compute + zero lateral -----------------------------------
    float sum = 0.0f;
    int c = t & 31;          // lane: uchar4 group along vz (vz = 4c..4c+3)
    int w = t >> 5;          // warp: 4 vy values each
    uchar4 zc; zc.x = zc.y = zc.z = zc.w = 0;
    #pragma unroll
    for (int ii = 0; ii < 4; ii++) {
        int vyl = w * 4 + ii;                    // 0..31
        int vy  = vy0 + vyl;
        int idx4 = vx * 4096 + vy * 32 + c;      // uchar4 / float4 index
        uchar4 L0 = reinterpret_cast<const uchar4*>(g_vol[1])[idx4];
        uchar4 L1 = reinterpret_cast<const uchar4*>(g_vol[3])[idx4];
        reinterpret_cast<uchar4*>(g_vol[1])[idx4] = zc;   // consume-and-reset
        reinterpret_cast<uchar4*>(g_vol[3])[idx4] = zc;
        float4 g = reinterpret_cast<const float4*>(gt)[idx4];
        // one aligned word = frontal bytes vz 4c..4c+3 ; bank = (33*vyl + c) % 32
        unsigned int f0 = *reinterpret_cast<const unsigned int*>(&sT0[vyl * TROW + 4 * c]);
        unsigned int f1 = *reinterpret_cast<const unsigned int*>(&sT1[vyl * TROW + 4 * c]);
        sum += bce_term(g.x, (int)( f0        & 255u) + L0.x)
             + bce_term(g.x, (int)( f1        & 255u) + L1.x);
        sum += bce_term(g.y, (int)((f0 >>  8) & 255u) + L0.y)
             + bce_term(g.y, (int)((f1 >>  8) & 255u) + L1.y);
        sum += bce_term(g.z, (int)((f0 >> 16) & 255u) + L0.z)
             + bce_term(g.z, (int)((f1 >> 16) & 255u) + L1.z);
        sum += bce_term(g.w, (int)( f0 >> 24        ) + L0.w)
             + bce_term(g.w, (int)( f1 >> 24        ) + L1.w);
    }

    // --- block reduce -> global atomic -> last-block finalize --------------
    sum = warp_sum(sum);
    int lane = t & 31;
    if (lane == 0) sh[w] = sum;
    __syncthreads();
    if (w == 0) {
        float v = (lane < 8) ? sh[lane] : 0.0f;
        v = warp_sum(v);
        if (lane == 0) {
            atomicAdd(&g_acc, (double)v);
            __threadfence();
            unsigned int total = gridDim.x * gridDim.y;
            unsigned int done = atomicInc(&g_ctr, total - 1);   // self-resetting
            if (done == total - 1) {
                double acc = atomicAdd(&g_acc, 0.0);            // atomic read
                out[0] = (float)(-acc / (2.0 * (double)NVOX));  // /B /NVOX
                g_acc = 0.0;                                    // reset for next call
            }
        }
    }
}

// ---------------------------------------------------------------------------
extern "C" void kernel_launch(void* const* d_in, const int* in_sizes, int n_in,
                              void* d_out, int out_size)
{
    const float* predF = (const float*)d_in[0];
    const float* predL = (const float*)d_in[1];
    const float* srcF  = (const float*)d_in[2];
    const float* tgtF  = (const float*)d_in[3];
    const float* srcL  = (const float*)d_in[4];
    const float* tgtL  = (const float*)d_in[5];
    const float* gt    = (const float*)d_in[6];
    const float* Ainv  = (const float*)d_in[7];
    const float* tinv  = (const float*)d_in[8];
    float* out = (float*)d_out;

    dim3 bp_grid((NPIX + 255) / 256, 4);
    bp_kernel<<<bp_grid, 256>>>(predF, predL, srcF, tgtF, srcL, tgtL, Ainv, tinv);

    dim3 rd_grid(VDIM, 4);   // 512 blocks
    reduce_kernel<<<rd_grid, 256>>>(gt, out);
}